// round 15
// baseline (speedup 1.0000x reference)
#include <cuda_runtime.h>
#include <cuda_bf16.h>
#include <float.h>
#include <cstdint>

// Problem shape (fixed per reference)
#define BATCH 32
#define SEQ   4096
#define HID   1024
#define TOP   512
#define CATK  (2*HID + TOP)   // 2560

#define NSPLIT 32                        // S-splits per batch in attention pass
#define ROWS_PER_SPLIT (SEQ / NSPLIT)    // 128 rows per CTA
#define WARPS 8
#define ROWS_PER_WARP (ROWS_PER_SPLIT / WARPS)  // 16 rows per warp
#define VPL 8                            // float4 per lane per row (1024/4/32)
#define ATTN_SMEM (WARPS * 2 * 256 * 16) // 64 KB: per-warp double row buffer

#define GEMM_BH 4                        // batches per GEMM CTA (8 slices)
#define GEMM_HW 4                        // h-rows per warp
#define GEMM_TILE_B (GEMM_BH * 64 * 16)  // bytes per tile buffer (4 KB)
#define GEMM_YB (BATCH / GEMM_BH)        // 8 gemm y-slices

// ---------------- scratch (__device__ globals; no allocations) --------------
__device__ float g_gamma [BATCH * HID];
__device__ float g_scores[BATCH * SEQ];
__device__ float g_cpart [BATCH * NSPLIT * HID];
__device__ float g_mzpart[BATCH * NSPLIT * 2];
__device__ float g_cat   [BATCH * CATK];
__device__ int   g_done  [BATCH];        // zero-init; reset by finisher CTA

__device__ __forceinline__ float dot4(float4 a, float4 b)
{
    return a.x * b.x + a.y * b.y + a.z * b.z + a.w * b.w;
}

// recompute global (m, 1/Z) for batch b from the tiny per-split table
__device__ __forceinline__ void softmax_mz(int b, float& mg, float& inv)
{
    mg = -FLT_MAX;
    #pragma unroll
    for (int i = 0; i < NSPLIT; ++i)
        mg = fmaxf(mg, g_mzpart[(b * NSPLIT + i) * 2 + 0]);
    float Zg = 0.f;
    #pragma unroll
    for (int i = 0; i < NSPLIT; ++i) {
        float mi = g_mzpart[(b * NSPLIT + i) * 2 + 0];
        float zi = g_mzpart[(b * NSPLIT + i) * 2 + 1];
        Zg += zi * __expf(mi - mg);
    }
    inv = 1.f / Zg;
}

// ---------------------------------------------------------------------------
// Kernel 1: small GEMM  out[b][h] = act( bias[h] + sum_k in[b][k]*W[h][k] )
// grid = (Hout/32, GEMM_YB + wq), block = 256.
//   y <  GEMM_YB : GEMM slice — warp owns 4 h rows, CTA one 4-batch slice.
//                  Ring-4 cp.async tile buffers, ONE barrier per chunk.
//   y >= GEMM_YB : softmax-weights CTA (gemm2 only): batch = blockIdx.x,
//                  quarter = y - GEMM_YB. Overlaps GEMM compute.
// K: multiple of 256, >= 512. Hout/32 must equal BATCH for weights path.
// ---------------------------------------------------------------------------
__device__ __forceinline__ void stage_tile(uint32_t dst, const float* __restrict__ in,
                                           int b0, int K, int k0, int t)
{
    // 256 float4 total (4 KB), one per thread
    int bb = t >> 6;
    int kk = t & 63;
    const float4* src = (const float4*)(in + (size_t)(b0 + bb) * K + k0) + kk;
    asm volatile("cp.async.cg.shared.global [%0], [%1], 16;\n"
                 :: "r"(dst + t * 16), "l"(src));
}

__global__ void __launch_bounds__(256)
small_gemm_kernel(const float* __restrict__ in, const float* __restrict__ W,
                  const float* __restrict__ bias, float* __restrict__ out,
                  int K, int Hout, int act, float* __restrict__ out_w)
{
    const int t = threadIdx.x;

    // ---- overlapped softmax-weights path (gemm2 launch only) ----
    if (blockIdx.y >= GEMM_YB) {
        const int b = blockIdx.x;                 // 0..31 (= Hout/32 for HID)
        const int q = blockIdx.y - GEMM_YB;       // 0..3
        float mg, inv;
        softmax_mz(b, mg, inv);
        const float4* sc = (const float4*)(g_scores + (size_t)b * SEQ + q * (SEQ / 4));
        float4*       ow = (float4*)(out_w + (size_t)b * SEQ + q * (SEQ / 4));
        float4 s = sc[t];
        float4 w;
        w.x = __expf(s.x - mg) * inv;
        w.y = __expf(s.y - mg) * inv;
        w.z = __expf(s.z - mg) * inv;
        w.w = __expf(s.w - mg) * inv;
        ow[t] = w;
        return;
    }

    // ---- GEMM path ----
    __shared__ float4 tile[4][GEMM_BH * 64];   // ring of 4, 16 KB
    const int warp = t >> 5;
    const int lane = t & 31;
    const int hb   = blockIdx.x * 32 + warp * GEMM_HW;   // first h of this warp
    const int b0   = blockIdx.y * GEMM_BH;
    const int N    = K / 256;                  // chunks (4 or 10)

    const uint32_t tbase = (uint32_t)__cvta_generic_to_shared(tile);

    // prologue: stage chunks 0,1 into buffers 0,1
    stage_tile(tbase,               in, b0, K, 0,   t);
    asm volatile("cp.async.commit_group;\n");
    stage_tile(tbase + GEMM_TILE_B, in, b0, K, 256, t);
    asm volatile("cp.async.commit_group;\n");

    const float4* Wp[GEMM_HW];
    #pragma unroll
    for (int h = 0; h < GEMM_HW; ++h)
        Wp[h] = (const float4*)(W + (size_t)(hb + h) * K);   // 64 float4/chunk

    // current-chunk W registers (chunk 0)
    float4 w[GEMM_HW][2];
    #pragma unroll
    for (int h = 0; h < GEMM_HW; ++h) {
        w[h][0] = Wp[h][lane];
        w[h][1] = Wp[h][32 + lane];
    }

    float acc[GEMM_HW][GEMM_BH];
    #pragma unroll
    for (int h = 0; h < GEMM_HW; ++h)
        #pragma unroll
        for (int b = 0; b < GEMM_BH; ++b) acc[h][b] = 0.f;

    for (int ci = 0; ci < N; ++ci) {
        // prefetch next chunk's W into registers (overlaps FFMA below)
        float4 nw[GEMM_HW][2];
        if (ci + 1 < N) {
            #pragma unroll
            for (int h = 0; h < GEMM_HW; ++h) {
                const float4* p = Wp[h] + (ci + 1) * 64;
                nw[h][0] = p[lane];
                nw[h][1] = p[32 + lane];
            }
        } else {
            #pragma unroll
            for (int h = 0; h < GEMM_HW; ++h)
                nw[h][0] = nw[h][1] = make_float4(0.f, 0.f, 0.f, 0.f);
        }

        asm volatile("cp.async.wait_group 1;\n");
        __syncthreads();                       // tile[ci&3] ready; also
                                               // guarantees prior reads of the
                                               // buffer restaged below are done
        const float4* tl = tile[ci & 3];
        #pragma unroll
        for (int half = 0; half < 2; ++half)
            #pragma unroll
            for (int bb = 0; bb < GEMM_BH; ++bb) {
                float4 xv = tl[bb * 64 + half * 32 + lane];
                #pragma unroll
                for (int h = 0; h < GEMM_HW; ++h)
                    acc[h][bb] += dot4(w[h][half], xv);
            }

        // restage 2 ahead into buffer (ci+2)&3 — distinct from the read buffer
        if (ci + 2 < N)
            stage_tile(tbase + ((ci + 2) & 3) * GEMM_TILE_B, in, b0, K,
                       (ci + 2) * 256, t);
        asm volatile("cp.async.commit_group;\n");   // empty group ok

        #pragma unroll
        for (int h = 0; h < GEMM_HW; ++h) {
            w[h][0] = nw[h][0];
            w[h][1] = nw[h][1];
        }
    }

    #pragma unroll
    for (int off = 16; off; off >>= 1)
        #pragma unroll
        for (int h = 0; h < GEMM_HW; ++h)
            #pragma unroll
            for (int bb = 0; bb < GEMM_BH; ++bb)
                acc[h][bb] += __shfl_xor_sync(0xFFFFFFFFu, acc[h][bb], off);

    // epilogue: lanes 0-15 each write one (h, b): h = lane>>2, b = lane&3
    if (lane < 16) {
        const int hl = lane >> 2;
        const int bl = lane & 3;
        float v = acc[hl][bl] + bias[hb + hl];
        if (act) v = tanhf(v);
        out[(size_t)(b0 + bl) * Hout + hb + hl] = v;
    }
}

// ---------------------------------------------------------------------------
// Kernel 2: warp-autonomous fused scores + online softmax + weighted sum,
// cp.async double-buffered row staging. grid = (NSPLIT, BATCH), block = 256.
// The LAST split-CTA to finish each batch also performs the cross-split
// reduction and builds cat = [c_t | x | topic] (fused reduce_c).
// ---------------------------------------------------------------------------
__device__ __forceinline__ void stage_row(uint32_t dst_base, const float4* src)
{
    #pragma unroll
    for (int i = 0; i < VPL; ++i)
        asm volatile("cp.async.cg.shared.global [%0], [%1], 16;\n"
                     :: "r"(dst_base + i * 512), "l"(src + i * 32));
}

__global__ void __launch_bounds__(256, 2)
attn_pass_kernel(const float* __restrict__ ctx, const float* __restrict__ x,
                 const float* __restrict__ topic)
{
    extern __shared__ float4 sbuf[];          // [WARPS][2][256] float4
    __shared__ float s_m[WARPS], s_Z[WARPS];
    __shared__ int   s_last;

    const int t     = threadIdx.x;
    const int warp  = t >> 5;
    const int lane  = t & 31;
    const int split = blockIdx.x;
    const int b     = blockIdx.y;

    float4 g[VPL];
    {
        const float4* gp = (const float4*)(g_gamma + (size_t)b * HID);
        #pragma unroll
        for (int i = 0; i < VPL; ++i) g[i] = gp[lane + 32 * i];
    }

    const int row0 = split * ROWS_PER_SPLIT + warp * ROWS_PER_WARP;
    const float4* base = (const float4*)(ctx + ((size_t)b * SEQ + row0) * HID);

    float4* wbuf = sbuf + warp * 2 * 256;
    const uint32_t wbuf_addr =
        (uint32_t)__cvta_generic_to_shared(wbuf) + (uint32_t)lane * 16;

    #pragma unroll
    for (int pre = 0; pre < 2; ++pre) {
        stage_row(wbuf_addr + pre * 4096, base + pre * 256 + lane);
        asm volatile("cp.async.commit_group;\n");
    }

    float  m = -FLT_MAX, Z = 0.f;
    float4 c[VPL];
    #pragma unroll
    for (int i = 0; i < VPL; ++i) c[i] = make_float4(0.f, 0.f, 0.f, 0.f);

    for (int r = 0; r < ROWS_PER_WARP; ++r) {
        asm volatile("cp.async.wait_group 1;\n");
        __syncwarp();

        const float4* vbuf = wbuf + (r & 1) * 256;
        float4 v[VPL];
        #pragma unroll
        for (int i = 0; i < VPL; ++i) v[i] = vbuf[lane + 32 * i];
        __syncwarp();

        if (r + 2 < ROWS_PER_WARP)
            stage_row(wbuf_addr + (r & 1) * 4096, base + (r + 2) * 256 + lane);
        asm volatile("cp.async.commit_group;\n");

        float p = 0.f;
        #pragma unroll
        for (int i = 0; i < VPL; ++i)
            p += v[i].x * g[i].x + v[i].y * g[i].y + v[i].z * g[i].z + v[i].w * g[i].w;

        #pragma unroll
        for (int off = 16; off; off >>= 1)
            p += __shfl_xor_sync(0xFFFFFFFFu, p, off);

        if (lane == 0) g_scores[(size_t)b * SEQ + row0 + r] = p;

        if (p > m) {
            const float scale = __expf(m - p);
            Z *= scale;
            #pragma unroll
            for (int i = 0; i < VPL; ++i) {
                c[i].x *= scale; c[i].y *= scale;
                c[i].z *= scale; c[i].w *= scale;
            }
            m = p;
        }
        const float e = __expf(p - m);
        Z += e;
        #pragma unroll
        for (int i = 0; i < VPL; ++i) {
            c[i].x += e * v[i].x;  c[i].y += e * v[i].y;
            c[i].z += e * v[i].z;  c[i].w += e * v[i].w;
        }
    }

    asm volatile("cp.async.wait_group 0;\n");
    __syncthreads();
    float* s_c = (float*)sbuf;
    #pragma unroll
    for (int i = 0; i < VPL; ++i)
        ((float4*)(s_c + warp * HID))[lane + 32 * i] = c[i];
    if (lane == 0) { s_m[warp] = m; s_Z[warp] = Z; }
    __syncthreads();

    float mg = s_m[0];
    #pragma unroll
    for (int w = 1; w < WARPS; ++w) mg = fmaxf(mg, s_m[w]);

    float wsc[WARPS], Zg = 0.f;
    #pragma unroll
    for (int w = 0; w < WARPS; ++w) {
        wsc[w] = __expf(s_m[w] - mg);
        Zg += s_Z[w] * wsc[w];
    }

    float4 acc = make_float4(0.f, 0.f, 0.f, 0.f);
    #pragma unroll
    for (int w = 0; w < WARPS; ++w) {
        float4 cw = ((const float4*)(s_c + w * HID))[t];
        acc.x += wsc[w] * cw.x;  acc.y += wsc[w] * cw.y;
        acc.z += wsc[w] * cw.z;  acc.w += wsc[w] * cw.w;
    }
    ((float4*)(g_cpart + ((size_t)b * NSPLIT + split) * HID))[t] = acc;
    if (t == 0) {
        g_mzpart[(b * NSPLIT + split) * 2 + 0] = mg;
        g_mzpart[(b * NSPLIT + split) * 2 + 1] = Zg;
    }

    // ---- fused cross-split reduce: last CTA of this batch does it ----
    __threadfence();                          // publish cpart/mzpart (release)
    if (t == 0) {
        int old = atomicAdd(&g_done[b], 1);
        s_last = (old == NSPLIT - 1) ? 1 : 0;
    }
    __syncthreads();
    if (!s_last) return;
    __threadfence();                          // acquire others' writes

    float mgg, inv;
    softmax_mz(b, mgg, inv);

    float4 cc = make_float4(0.f, 0.f, 0.f, 0.f);
    #pragma unroll
    for (int i = 0; i < NSPLIT; ++i) {
        const float wi = __expf(g_mzpart[(b * NSPLIT + i) * 2 + 0] - mgg);
        float4 cp = ((const float4*)(g_cpart + ((size_t)b * NSPLIT + i) * HID))[t];
        cc.x += wi * cp.x;  cc.y += wi * cp.y;
        cc.z += wi * cp.z;  cc.w += wi * cp.w;
    }
    cc.x *= inv; cc.y *= inv; cc.z *= inv; cc.w *= inv;

    ((float4*)(g_cat + (size_t)b * CATK))[t] = cc;
    ((float4*)(g_cat + (size_t)b * CATK + HID))[t] =
        ((const float4*)(x + (size_t)b * HID))[t];
    if (t < TOP / 4)
        ((float4*)(g_cat + (size_t)b * CATK + 2 * HID))[t] =
            ((const float4*)(topic + (size_t)b * TOP))[t];

    if (t == 0) g_done[b] = 0;                // reset for next graph replay
}

// ---------------------------------------------------------------------------
extern "C" void kernel_launch(void* const* d_in, const int* in_sizes, int n_in,
                              void* d_out, int out_size)
{
    const float* x     = (const float*)d_in[0];
    const float* ctx   = (const float*)d_in[1];
    const float* topic = (const float*)d_in[2];
    const float* W_in  = (const float*)d_in[3];
    const float* b_in  = (const float*)d_in[4];
    const float* W_out = (const float*)d_in[5];
    const float* b_out = (const float*)d_in[6];

    float* out  = (float*)d_out;                 // [BATCH,HID] output
    float* outw = out + BATCH * HID;             // [BATCH,SEQ] weights

    float* gamma_ptr;
    cudaGetSymbolAddress((void**)&gamma_ptr, g_gamma);
    float* cat_ptr;
    cudaGetSymbolAddress((void**)&cat_ptr, g_cat);

    static int smem_set = 0;
    if (!smem_set) {
        cudaFuncSetAttribute(attn_pass_kernel,
                             cudaFuncAttributeMaxDynamicSharedMemorySize,
                             ATTN_SMEM);
        smem_set = 1;
    }

    // 1) gamma = x @ W_in^T + b_in   (no weights CTAs)
    small_gemm_kernel<<<dim3(HID / 32, GEMM_YB), 256>>>(
        x, W_in, b_in, gamma_ptr, HID, HID, 0, nullptr);

    // 2) fused scores + online softmax + partial c_t + (last-CTA) reduce/cat
    attn_pass_kernel<<<dim3(NSPLIT, BATCH), 256, ATTN_SMEM>>>(ctx, x, topic);

    // 3) output = tanh(cat @ W_out^T + b_out), with 128 overlapped
    //    softmax-weights CTAs (grid.y 8..11)
    small_gemm_kernel<<<dim3(HID / 32, GEMM_YB + 4), 256>>>(
        cat_ptr, W_out, b_out, out, CATK, HID, 1, outw);
}

// round 16
// speedup vs baseline: 1.1265x; 1.1265x over previous
#include <cuda_runtime.h>
#include <cuda_bf16.h>
#include <float.h>
#include <cstdint>

// Problem shape (fixed per reference)
#define BATCH 32
#define SEQ   4096
#define HID   1024
#define TOP   512
#define CATK  (2*HID + TOP)   // 2560

#define NSPLIT 16                        // S-splits per batch in attention pass
#define ROWS_PER_SPLIT (SEQ / NSPLIT)    // 256 rows per CTA
#define WARPS 8
#define ROWS_PER_WARP (ROWS_PER_SPLIT / WARPS)  // 32 rows per warp
#define VPL 8                            // float4 per lane per row (1024/4/32)
#define ATTN_SMEM (WARPS * 2 * 256 * 16) // 64 KB: per-warp double row buffer

#define GEMM_BH 4                        // batches per GEMM CTA (8 slices)
#define GEMM_HW 4                        // h-rows per warp
#define GEMM_TILE_B (GEMM_BH * 64 * 16)  // bytes per tile buffer (4 KB)
#define GEMM_YB (BATCH / GEMM_BH)        // 8 gemm y-slices

// packed fp32x2 FMA (Blackwell): d = a*b + d, elementwise on {lo,hi}
#define FMA_F32X2(d, a, b) \
    asm("fma.rn.f32x2 %0, %1, %2, %0;" : "+l"(d) : "l"(a), "l"(b))
#define UNPACK_F32X2(lo, hi, p) \
    asm("mov.b64 {%0, %1}, %2;" : "=f"(lo), "=f"(hi) : "l"(p))

// ---------------- scratch (__device__ globals; no allocations) --------------
__device__ float g_gamma [BATCH * HID];
__device__ float g_scores[BATCH * SEQ];
__device__ float g_cpart [BATCH * NSPLIT * HID];
__device__ float g_mzpart[BATCH * NSPLIT * 2];
__device__ float g_cat   [BATCH * CATK];

__device__ __forceinline__ float dot4(float4 a, float4 b)
{
    return a.x * b.x + a.y * b.y + a.z * b.z + a.w * b.w;
}

// recompute global (m, 1/Z) for batch b from the tiny per-split table
__device__ __forceinline__ void softmax_mz(int b, float& mg, float& inv)
{
    mg = -FLT_MAX;
    #pragma unroll
    for (int i = 0; i < NSPLIT; ++i)
        mg = fmaxf(mg, g_mzpart[(b * NSPLIT + i) * 2 + 0]);
    float Zg = 0.f;
    #pragma unroll
    for (int i = 0; i < NSPLIT; ++i) {
        float mi = g_mzpart[(b * NSPLIT + i) * 2 + 0];
        float zi = g_mzpart[(b * NSPLIT + i) * 2 + 1];
        Zg += zi * __expf(mi - mg);
    }
    inv = 1.f / Zg;
}

// ---------------------------------------------------------------------------
// Kernel 1: small GEMM  out[b][h] = act( bias[h] + sum_k in[b][k]*W[h][k] )
// grid = (Hout/32, GEMM_YB + wq), block = 256.
//   y <  GEMM_YB : GEMM slice — warp owns 4 h rows, CTA one 4-batch slice.
//                  Ring-4 cp.async tile buffers; f32x2 packed FMA over K-pairs.
//   y >= GEMM_YB : softmax-weights CTA (gemm2 only): batch = blockIdx.x,
//                  quarter = y - GEMM_YB. Overlaps GEMM compute.
// K: multiple of 256, >= 512. Hout/32 must equal BATCH for weights path.
// ---------------------------------------------------------------------------
__device__ __forceinline__ void stage_tile(uint32_t dst, const float* __restrict__ in,
                                           int b0, int K, int k0, int t)
{
    // 256 float4 total (4 KB), one per thread
    int bb = t >> 6;
    int kk = t & 63;
    const float4* src = (const float4*)(in + (size_t)(b0 + bb) * K + k0) + kk;
    asm volatile("cp.async.cg.shared.global [%0], [%1], 16;\n"
                 :: "r"(dst + t * 16), "l"(src));
}

__global__ void __launch_bounds__(256, 2)
small_gemm_kernel(const float* __restrict__ in, const float* __restrict__ W,
                  const float* __restrict__ bias, float* __restrict__ out,
                  int K, int Hout, int act, float* __restrict__ out_w)
{
    const int t = threadIdx.x;

    // ---- overlapped softmax-weights path (gemm2 launch only) ----
    if (blockIdx.y >= GEMM_YB) {
        const int b = blockIdx.x;                 // 0..31 (= Hout/32 for HID)
        const int q = blockIdx.y - GEMM_YB;       // 0..3
        float mg, inv;
        softmax_mz(b, mg, inv);
        const float4* sc = (const float4*)(g_scores + (size_t)b * SEQ + q * (SEQ / 4));
        float4*       ow = (float4*)(out_w + (size_t)b * SEQ + q * (SEQ / 4));
        float4 s = sc[t];
        float4 w;
        w.x = __expf(s.x - mg) * inv;
        w.y = __expf(s.y - mg) * inv;
        w.z = __expf(s.z - mg) * inv;
        w.w = __expf(s.w - mg) * inv;
        ow[t] = w;
        return;
    }

    // ---- GEMM path ----
    __shared__ float4 tile[4][GEMM_BH * 64];   // ring of 4, 16 KB
    const int warp = t >> 5;
    const int lane = t & 31;
    const int hb   = blockIdx.x * 32 + warp * GEMM_HW;   // first h of this warp
    const int b0   = blockIdx.y * GEMM_BH;
    const int N    = K / 256;                  // chunks (4 or 10)

    const uint32_t tbase = (uint32_t)__cvta_generic_to_shared(tile);

    // prologue: stage chunks 0,1 into buffers 0,1
    stage_tile(tbase,               in, b0, K, 0,   t);
    asm volatile("cp.async.commit_group;\n");
    stage_tile(tbase + GEMM_TILE_B, in, b0, K, 256, t);
    asm volatile("cp.async.commit_group;\n");

    const ulonglong2* Wp[GEMM_HW];
    #pragma unroll
    for (int h = 0; h < GEMM_HW; ++h)
        Wp[h] = (const ulonglong2*)(W + (size_t)(hb + h) * K);   // 64 ull2/chunk

    // current-chunk W registers (chunk 0), as packed f32x2 pairs
    ulonglong2 w2[GEMM_HW][2];
    #pragma unroll
    for (int h = 0; h < GEMM_HW; ++h) {
        w2[h][0] = Wp[h][lane];
        w2[h][1] = Wp[h][32 + lane];
    }

    // packed accumulators: {even-k partial, odd-k partial}
    unsigned long long acc2[GEMM_HW][GEMM_BH];
    #pragma unroll
    for (int h = 0; h < GEMM_HW; ++h)
        #pragma unroll
        for (int b = 0; b < GEMM_BH; ++b) acc2[h][b] = 0ULL;

    for (int ci = 0; ci < N; ++ci) {
        // prefetch next chunk's W into registers (overlaps FMA below)
        ulonglong2 nw2[GEMM_HW][2];
        if (ci + 1 < N) {
            #pragma unroll
            for (int h = 0; h < GEMM_HW; ++h) {
                const ulonglong2* p = Wp[h] + (ci + 1) * 64;
                nw2[h][0] = p[lane];
                nw2[h][1] = p[32 + lane];
            }
        } else {
            #pragma unroll
            for (int h = 0; h < GEMM_HW; ++h) {
                nw2[h][0] = make_ulonglong2(0ULL, 0ULL);
                nw2[h][1] = make_ulonglong2(0ULL, 0ULL);
            }
        }

        asm volatile("cp.async.wait_group 1;\n");
        __syncthreads();                       // tile[ci&3] ready; also
                                               // guarantees prior reads of the
                                               // buffer restaged below are done
        const ulonglong2* tl = (const ulonglong2*)tile[ci & 3];
        #pragma unroll
        for (int half = 0; half < 2; ++half)
            #pragma unroll
            for (int bb = 0; bb < GEMM_BH; ++bb) {
                ulonglong2 xv = tl[bb * 64 + half * 32 + lane];
                #pragma unroll
                for (int h = 0; h < GEMM_HW; ++h) {
                    FMA_F32X2(acc2[h][bb], w2[h][half].x, xv.x);
                    FMA_F32X2(acc2[h][bb], w2[h][half].y, xv.y);
                }
            }

        // restage 2 ahead into buffer (ci+2)&3 — distinct from the read buffer
        if (ci + 2 < N)
            stage_tile(tbase + ((ci + 2) & 3) * GEMM_TILE_B, in, b0, K,
                       (ci + 2) * 256, t);
        asm volatile("cp.async.commit_group;\n");   // empty group ok

        #pragma unroll
        for (int h = 0; h < GEMM_HW; ++h) {
            w2[h][0] = nw2[h][0];
            w2[h][1] = nw2[h][1];
        }
    }

    // unpack even/odd partials, then cross-lane reduce
    float acc[GEMM_HW][GEMM_BH];
    #pragma unroll
    for (int h = 0; h < GEMM_HW; ++h)
        #pragma unroll
        for (int bb = 0; bb < GEMM_BH; ++bb) {
            float lo, hi;
            UNPACK_F32X2(lo, hi, acc2[h][bb]);
            acc[h][bb] = lo + hi;
        }

    #pragma unroll
    for (int off = 16; off; off >>= 1)
        #pragma unroll
        for (int h = 0; h < GEMM_HW; ++h)
            #pragma unroll
            for (int bb = 0; bb < GEMM_BH; ++bb)
                acc[h][bb] += __shfl_xor_sync(0xFFFFFFFFu, acc[h][bb], off);

    // epilogue: lanes 0-15 each write one (h, b): h = lane>>2, b = lane&3
    if (lane < 16) {
        const int hl = lane >> 2;
        const int bl = lane & 3;
        float v = acc[hl][bl] + bias[hb + hl];
        if (act) v = tanhf(v);
        out[(size_t)(b0 + bl) * Hout + hb + hl] = v;
    }
}

// ---------------------------------------------------------------------------
// Kernel 2: warp-autonomous fused scores + online softmax + weighted sum,
// with cp.async double-buffered row staging. grid = (NSPLIT, BATCH), block=256.
// ---------------------------------------------------------------------------
__device__ __forceinline__ void stage_row(uint32_t dst_base, const float4* src)
{
    #pragma unroll
    for (int i = 0; i < VPL; ++i)
        asm volatile("cp.async.cg.shared.global [%0], [%1], 16;\n"
                     :: "r"(dst_base + i * 512), "l"(src + i * 32));
}

__global__ void __launch_bounds__(256, 2)
attn_pass_kernel(const float* __restrict__ ctx)
{
    extern __shared__ float4 sbuf[];          // [WARPS][2][256] float4
    __shared__ float s_m[WARPS], s_Z[WARPS];

    const int t     = threadIdx.x;
    const int warp  = t >> 5;
    const int lane  = t & 31;
    const int split = blockIdx.x;
    const int b     = blockIdx.y;

    float4 g[VPL];
    {
        const float4* gp = (const float4*)(g_gamma + (size_t)b * HID);
        #pragma unroll
        for (int i = 0; i < VPL; ++i) g[i] = gp[lane + 32 * i];
    }

    const int row0 = split * ROWS_PER_SPLIT + warp * ROWS_PER_WARP;
    const float4* base = (const float4*)(ctx + ((size_t)b * SEQ + row0) * HID);

    float4* wbuf = sbuf + warp * 2 * 256;
    const uint32_t wbuf_addr =
        (uint32_t)__cvta_generic_to_shared(wbuf) + (uint32_t)lane * 16;

    #pragma unroll
    for (int pre = 0; pre < 2; ++pre) {
        stage_row(wbuf_addr + pre * 4096, base + pre * 256 + lane);
        asm volatile("cp.async.commit_group;\n");
    }

    float  m = -FLT_MAX, Z = 0.f;
    float4 c[VPL];
    #pragma unroll
    for (int i = 0; i < VPL; ++i) c[i] = make_float4(0.f, 0.f, 0.f, 0.f);

    for (int r = 0; r < ROWS_PER_WARP; ++r) {
        asm volatile("cp.async.wait_group 1;\n");
        __syncwarp();

        const float4* vbuf = wbuf + (r & 1) * 256;
        float4 v[VPL];
        #pragma unroll
        for (int i = 0; i < VPL; ++i) v[i] = vbuf[lane + 32 * i];
        __syncwarp();

        if (r + 2 < ROWS_PER_WARP)
            stage_row(wbuf_addr + (r & 1) * 4096, base + (r + 2) * 256 + lane);
        asm volatile("cp.async.commit_group;\n");

        float p = 0.f;
        #pragma unroll
        for (int i = 0; i < VPL; ++i)
            p += v[i].x * g[i].x + v[i].y * g[i].y + v[i].z * g[i].z + v[i].w * g[i].w;

        #pragma unroll
        for (int off = 16; off; off >>= 1)
            p += __shfl_xor_sync(0xFFFFFFFFu, p, off);

        if (lane == 0) g_scores[(size_t)b * SEQ + row0 + r] = p;

        if (p > m) {
            const float scale = __expf(m - p);
            Z *= scale;
            #pragma unroll
            for (int i = 0; i < VPL; ++i) {
                c[i].x *= scale; c[i].y *= scale;
                c[i].z *= scale; c[i].w *= scale;
            }
            m = p;
        }
        const float e = __expf(p - m);
        Z += e;
        #pragma unroll
        for (int i = 0; i < VPL; ++i) {
            c[i].x += e * v[i].x;  c[i].y += e * v[i].y;
            c[i].z += e * v[i].z;  c[i].w += e * v[i].w;
        }
    }

    asm volatile("cp.async.wait_group 0;\n");
    __syncthreads();
    float* s_c = (float*)sbuf;
    #pragma unroll
    for (int i = 0; i < VPL; ++i)
        ((float4*)(s_c + warp * HID))[lane + 32 * i] = c[i];
    if (lane == 0) { s_m[warp] = m; s_Z[warp] = Z; }
    __syncthreads();

    float mg = s_m[0];
    #pragma unroll
    for (int w = 1; w < WARPS; ++w) mg = fmaxf(mg, s_m[w]);

    float wsc[WARPS], Zg = 0.f;
    #pragma unroll
    for (int w = 0; w < WARPS; ++w) {
        wsc[w] = __expf(s_m[w] - mg);
        Zg += s_Z[w] * wsc[w];
    }

    float4 acc = make_float4(0.f, 0.f, 0.f, 0.f);
    #pragma unroll
    for (int w = 0; w < WARPS; ++w) {
        float4 cw = ((const float4*)(s_c + w * HID))[t];
        acc.x += wsc[w] * cw.x;  acc.y += wsc[w] * cw.y;
        acc.z += wsc[w] * cw.z;  acc.w += wsc[w] * cw.w;
    }
    ((float4*)(g_cpart + ((size_t)b * NSPLIT + split) * HID))[t] = acc;
    if (t == 0) {
        g_mzpart[(b * NSPLIT + split) * 2 + 0] = mg;
        g_mzpart[(b * NSPLIT + split) * 2 + 1] = Zg;
    }
}

// ---------------------------------------------------------------------------
// Kernel 3: cross-split reduction -> c_t; builds cat = [c_t | x | topic].
// grid = BATCH, block = 256. (Weights write lives in the gemm2 launch.)
// ---------------------------------------------------------------------------
__global__ void __launch_bounds__(256)
reduce_c_kernel(const float* __restrict__ x, const float* __restrict__ topic)
{
    const int b = blockIdx.x;
    const int t = threadIdx.x;

    float mg, inv;
    softmax_mz(b, mg, inv);

    float wsc[NSPLIT];
    #pragma unroll
    for (int i = 0; i < NSPLIT; ++i)
        wsc[i] = __expf(g_mzpart[(b * NSPLIT + i) * 2 + 0] - mg);

    float4 c = make_float4(0.f, 0.f, 0.f, 0.f);
    #pragma unroll
    for (int i = 0; i < NSPLIT; ++i) {
        float4 cp = ((const float4*)(g_cpart + ((size_t)b * NSPLIT + i) * HID))[t];
        c.x += wsc[i] * cp.x;  c.y += wsc[i] * cp.y;
        c.z += wsc[i] * cp.z;  c.w += wsc[i] * cp.w;
    }
    c.x *= inv; c.y *= inv; c.z *= inv; c.w *= inv;

    ((float4*)(g_cat + (size_t)b * CATK))[t] = c;
    ((float4*)(g_cat + (size_t)b * CATK + HID))[t] =
        ((const float4*)(x + (size_t)b * HID))[t];
    if (t < TOP / 4)
        ((float4*)(g_cat + (size_t)b * CATK + 2 * HID))[t] =
            ((const float4*)(topic + (size_t)b * TOP))[t];
}

// ---------------------------------------------------------------------------
extern "C" void kernel_launch(void* const* d_in, const int* in_sizes, int n_in,
                              void* d_out, int out_size)
{
    const float* x     = (const float*)d_in[0];
    const float* ctx   = (const float*)d_in[1];
    const float* topic = (const float*)d_in[2];
    const float* W_in  = (const float*)d_in[3];
    const float* b_in  = (const float*)d_in[4];
    const float* W_out = (const float*)d_in[5];
    const float* b_out = (const float*)d_in[6];

    float* out  = (float*)d_out;                 // [BATCH,HID] output
    float* outw = out + BATCH * HID;             // [BATCH,SEQ] weights

    float* gamma_ptr;
    cudaGetSymbolAddress((void**)&gamma_ptr, g_gamma);
    float* cat_ptr;
    cudaGetSymbolAddress((void**)&cat_ptr, g_cat);

    static int smem_set = 0;
    if (!smem_set) {
        cudaFuncSetAttribute(attn_pass_kernel,
                             cudaFuncAttributeMaxDynamicSharedMemorySize,
                             ATTN_SMEM);
        smem_set = 1;
    }

    // 1) gamma = x @ W_in^T + b_in   (no weights CTAs)
    small_gemm_kernel<<<dim3(HID / 32, GEMM_YB), 256>>>(
        x, W_in, b_in, gamma_ptr, HID, HID, 0, nullptr);

    // 2) fused scores + online softmax + partial c_t (single context pass)
    attn_pass_kernel<<<dim3(NSPLIT, BATCH), 256, ATTN_SMEM>>>(ctx);

    // 3) cross-split reduce + cat build
    reduce_c_kernel<<<BATCH, 256>>>(x, topic);

    // 4) output = tanh(cat @ W_out^T + b_out), with 128 overlapped
    //    softmax-weights CTAs (grid.y 8..11)
    small_gemm_kernel<<<dim3(HID / 32, GEMM_YB + 4), 256>>>(
        cat_ptr, W_out, b_out, out, CATK, HID, 1, outw);
}